// round 9
// baseline (speedup 1.0000x reference)
#include <cuda_runtime.h>
#include <cuda_fp16.h>
#include <cstdint>

// ---------------------------------------------------------------------------
// KAN forward: s8 2:4-sparse spline GEMM (mma.sp m16n8k64, layout validated
// by round-8 probe) + dense fp16 silu GEMM, fused, shared accumulators.
// Spline logical K=8192 ([ev|od] groups per feature), compressed 4096 s8.
// A quant: x190 (bases in [0,2/3]); B quant: per-output-column scale.
// Meta per row per 128k-stage: 16B stored permuted (w0,w2,w1,w3) so each
// thread fetches its two op-words with one LDS.64.
// ---------------------------------------------------------------------------

#define M_ROWS 4096
#define N_COLS 1024
#define BM 128
#define BN 256
#define NSP 64
#define NDN 16
#define NTOT (NSP + NDN)

__device__ __align__(16) uint8_t  g_A [(size_t)M_ROWS * 4096];  // comp s8 A
__device__ __align__(16) __half   g_As[(size_t)M_ROWS * 1024];  // silu
__device__ __align__(16) uint8_t  g_B [(size_t)N_COLS * 8192];  // s8 spline B
__device__ __align__(16) __half   g_Bb[(size_t)N_COLS * 1024];  // base W fp16
__device__ __align__(16) uint32_t g_M [(size_t)M_ROWS * 256];   // meta 1KB/row
__device__ float g_scale[N_COLS];

__device__ __forceinline__ uint32_t smem_u32(const void* p) {
    uint32_t a;
    asm("{ .reg .u64 t; cvta.to.shared.u64 t, %1; cvt.u32.u64 %0, t; }"
        : "=r"(a) : "l"(p));
    return a;
}
__device__ __forceinline__ void cp_async16(uint32_t s, const void* g) {
    asm volatile("cp.async.cg.shared.global [%0], [%1], 16;" :: "r"(s), "l"(g));
}
__device__ __forceinline__ void ldmatrix_x4(uint32_t* r, uint32_t addr) {
    asm volatile("ldmatrix.sync.aligned.m8n8.x4.shared.b16 {%0,%1,%2,%3}, [%4];"
                 : "=r"(r[0]), "=r"(r[1]), "=r"(r[2]), "=r"(r[3]) : "r"(addr));
}
__device__ __forceinline__ void mma_sp_s8(int* d, const uint32_t* a,
                                          const uint32_t* b, uint32_t e) {
    asm volatile(
        "mma.sp::ordered_metadata.sync.aligned.m16n8k64.row.col.s32.s8.s8.s32 "
        "{%0,%1,%2,%3}, {%4,%5,%6,%7}, {%8,%9,%10,%11}, {%0,%1,%2,%3}, %12, 0x0;"
        : "+r"(d[0]), "+r"(d[1]), "+r"(d[2]), "+r"(d[3])
        : "r"(a[0]), "r"(a[1]), "r"(a[2]), "r"(a[3]),
          "r"(b[0]), "r"(b[1]), "r"(b[2]), "r"(b[3]), "r"(e));
}
__device__ __forceinline__ void mma16816(float* d, const uint32_t* a,
                                         const uint32_t* b) {
    asm volatile(
        "mma.sync.aligned.m16n8k16.row.col.f32.f16.f16.f32 "
        "{%0,%1,%2,%3}, {%4,%5,%6,%7}, {%8,%9}, {%0,%1,%2,%3};"
        : "+f"(d[0]), "+f"(d[1]), "+f"(d[2]), "+f"(d[3])
        : "r"(a[0]), "r"(a[1]), "r"(a[2]), "r"(a[3]), "r"(b[0]), "r"(b[1]));
}

// ---------------------------------------------------------------------------
// Kernel 1: analytic spline -> s8 compressed A + permuted meta + fp16 silu.
// ---------------------------------------------------------------------------
__global__ void build_A_kernel(const float* __restrict__ x) {
    __shared__ unsigned char nib[512];
    const int t  = threadIdx.x;
    const int b  = blockIdx.x >> 2;
    const int i0 = (blockIdx.x & 3) << 8;

    float xv = x[b * 1024 + i0 + t];
    g_As[(size_t)b * 1024 + i0 + t] = __float2half(xv / (1.0f + __expf(-xv)));

    int j = (int)floorf((xv + 2.2f) * 2.5f);
    bool ok = (j >= 0) && (j <= 10);
    float tj = (float)(j - 3) * 0.4f - 1.0f;
    float u  = (xv - tj) * 2.5f;
    float um = 1.0f - u;
    float u2 = u * u, u3 = u2 * u;
    float W0 = um * um * um * (1.0f / 6.0f);
    float W1 = (3.0f * u3 - 6.0f * u2 + 4.0f) * (1.0f / 6.0f);
    float W2 = (-3.0f * u3 + 3.0f * u2 + 3.0f * u + 1.0f) * (1.0f / 6.0f);
    float W3 = u3 * (1.0f / 6.0f);
    if (!ok) { W0 = W1 = W2 = W3 = 0.0f; }

    int   qe  = (j + 1) & 1;
    int   pe  = j - 3 + qe;
    float We0 = qe ? W1 : W0, We1 = qe ? W3 : W2;
    int   e0  = max(min(pe >> 1, 2), 0), e1 = e0 + 1;
    float ve0 = (2 * e0 == pe) ? We0 : ((2 * e0 == pe + 2) ? We1 : 0.0f);
    float ve1 = (2 * e1 == pe) ? We0 : ((2 * e1 == pe + 2) ? We1 : 0.0f);
    int   qo  = qe ^ 1;
    int   po  = j - 3 + qo;
    float Wo0 = qo ? W1 : W0, Wo1 = qo ? W3 : W2;
    int   o0  = max(min(po >> 1, 2), 0), o1 = o0 + 1;
    float vo0 = (2 * o0 + 1 == po) ? Wo0 : ((2 * o0 + 1 == po + 2) ? Wo1 : 0.0f);
    float vo1 = (2 * o1 + 1 == po) ? Wo0 : ((2 * o1 + 1 == po + 2) ? Wo1 : 0.0f);

    uint32_t q0 = (uint32_t)(uint8_t)(int8_t)__float2int_rn(ve0 * 190.0f);
    uint32_t q1 = (uint32_t)(uint8_t)(int8_t)__float2int_rn(ve1 * 190.0f);
    uint32_t q2 = (uint32_t)(uint8_t)(int8_t)__float2int_rn(vo0 * 190.0f);
    uint32_t q3 = (uint32_t)(uint8_t)(int8_t)__float2int_rn(vo1 * 190.0f);
    *(uint32_t*)(g_A + (size_t)b * 4096 + (size_t)(i0 + t) * 4) =
        q0 | (q1 << 8) | (q2 << 16) | (q3 << 24);

    nib[2 * t]     = (unsigned char)(e0 | (e1 << 2));
    nib[2 * t + 1] = (unsigned char)(o0 | (o1 << 2));
    __syncthreads();

    // pack 64 words; permute within each 4-word stage chunk: w -> (w&1)*8+(w>>1)*4
    if (t < 64) {
        uint32_t w = 0;
#pragma unroll
        for (int q = 0; q < 8; q++) w |= (uint32_t)nib[8 * t + q] << (4 * q);
        int W = (i0 >> 2) + t;          // global word index
        int s = W >> 2, widx = W & 3;
        *(uint32_t*)((char*)g_M + (size_t)b * 1024 + s * 16
                     + (widx & 1) * 8 + (widx >> 1) * 4) = w;
    }
}

// ---------------------------------------------------------------------------
// Kernel 2: per-column s8 weight quantization + fp16 base weights.
// ---------------------------------------------------------------------------
__global__ void pack_W_kernel(const float* __restrict__ bw,
                              const float* __restrict__ sw,
                              const float* __restrict__ ss) {
    __shared__ float red[256];
    const int t = threadIdx.x;
    const int o = blockIdx.x;

    float mx = 1e-20f;
#pragma unroll
    for (int it = 0; it < 4; it++) {
        int i = it * 256 + t;
        float sc = ss[o * 1024 + i];
        const float* swp = sw + ((size_t)o * 1024 + i) * 8;
#pragma unroll
        for (int k = 0; k < 8; k++) mx = fmaxf(mx, fabsf(swp[k] * sc));
    }
    red[t] = mx;
    __syncthreads();
    for (int s = 128; s > 0; s >>= 1) {
        if (t < s) red[t] = fmaxf(red[t], red[t + s]);
        __syncthreads();
    }
    const float m = red[0];
    const float inv = 127.0f / m;
    if (t == 0) g_scale[o] = m / (127.0f * 190.0f);

#pragma unroll
    for (int it = 0; it < 4; it++) {
        int i = it * 256 + t;
        float sc = ss[o * 1024 + i];
        const float* swp = sw + ((size_t)o * 1024 + i) * 8;
        uint32_t lo = 0, hi = 0;
#pragma unroll
        for (int k = 0; k < 4; k++) {
            lo |= ((uint32_t)(uint8_t)(int8_t)__float2int_rn(swp[2 * k] * sc * inv)) << (8 * k);
            hi |= ((uint32_t)(uint8_t)(int8_t)__float2int_rn(swp[2 * k + 1] * sc * inv)) << (8 * k);
        }
        *(uint2*)(g_B + (size_t)o * 8192 + (size_t)i * 8) = make_uint2(lo, hi);
        g_Bb[o * 1024 + i] = __float2half(bw[o * 1024 + i]);
    }
}

// ---------------------------------------------------------------------------
// Kernel 3: fused GEMM. 128x256 tile, 8 warps (2x4), warp tile 64x64,
// 3-stage cp.async pipeline. Stages 0..63: s8 sparse (128 logical k);
// 64..79: dense fp16 silu. Stage smem: A 18432 | meta 2048 | B 36864.
// ---------------------------------------------------------------------------
#define STG_A 18432
#define STG_M 2048
#define STG_B 36864
#define STG   (STG_A + STG_M + STG_B)   // 57344
#define SMEM_TOT (3 * STG)              // 172032

__global__ void __launch_bounds__(256, 1)
gemm_kernel(float* __restrict__ C) {
    extern __shared__ char smc[];
    const uint32_t sb = smem_u32(smc);
    const int tid  = threadIdx.x;
    const int wid  = tid >> 5;
    const int lane = tid & 31;
    const int wm   = (wid >> 2) * 64;
    const int wn   = (wid & 3) * 64;
    const int mBase = blockIdx.y * BM;
    const int nBase = blockIdx.x * BN;

    int acc[4][8][4];
#pragma unroll
    for (int mb = 0; mb < 4; mb++)
#pragma unroll
        for (int nb = 0; nb < 8; nb++)
#pragma unroll
            for (int r = 0; r < 4; r++) acc[mb][nb][r] = 0;

#define PRE(buf, it)                                                           \
    do {                                                                       \
        uint32_t d0 = sb + (buf) * STG;                                        \
        if ((it) < NSP) {                                                      \
            _Pragma("unroll")                                                  \
            for (int u = 0; u < 2; u++) { /* A: 128 x 64B comp s8 */           \
                int f = tid + u * 256, r = f >> 2, q = f & 3;                  \
                cp_async16(d0 + r * 144 + q * 16,                              \
                    g_A + (size_t)(mBase + r) * 4096 + (it) * 64 + q * 16);    \
            }                                                                  \
            if (tid < 128)                /* meta: 128 x 16B */                \
                cp_async16(d0 + STG_A + tid * 16,                              \
                    (const char*)g_M + (size_t)(mBase + tid) * 1024 +          \
                    (it) * 16);                                                \
            _Pragma("unroll")                                                  \
            for (int u = 0; u < 8; u++) { /* B: 256 x 128B s8 */               \
                int f = tid + u * 256, r = f >> 3, q = f & 7;                  \
                cp_async16(d0 + STG_A + STG_M + r * 144 + q * 16,              \
                    g_B + (size_t)(nBase + r) * 8192 + (it) * 128 + q * 16);   \
            }                                                                  \
        } else {                                                               \
            int itd = (it) - NSP;                                              \
            _Pragma("unroll")                                                  \
            for (int u = 0; u < 4; u++) { /* A: 128 x 128B fp16 */             \
                int f = tid + u * 256, r = f >> 3, q = f & 7;                  \
                cp_async16(d0 + r * 144 + q * 16,                              \
                    (const char*)g_As + (size_t)(mBase + r) * 2048 +           \
                    itd * 128 + q * 16);                                       \
            }                                                                  \
            _Pragma("unroll")                                                  \
            for (int u = 0; u < 8; u++) { /* B: 256 x 128B fp16 */             \
                int f = tid + u * 256, r = f >> 3, q = f & 7;                  \
                cp_async16(d0 + STG_A + STG_M + r * 144 + q * 16,              \
                    (const char*)g_Bb + (size_t)(nBase + r) * 2048 +           \
                    itd * 128 + q * 16);                                       \
            }                                                                  \
        }                                                                      \
        asm volatile("cp.async.commit_group;" ::: "memory");                   \
    } while (0)

    PRE(0, 0);
    PRE(1, 1);

    for (int it = 0; it < NTOT; it++) {
        const int buf = it % 3;
        if (it + 2 < NTOT) {
            PRE((it + 2) % 3, it + 2);
            asm volatile("cp.async.wait_group 2;" ::: "memory");
        } else {
            asm volatile("cp.async.wait_group 0;" ::: "memory");
        }
        __syncthreads();

        const uint32_t aB = sb + buf * STG;
        const uint32_t bB = aB + STG_A + STG_M;

        if (it < NSP) {
            const char* mB = smc + buf * STG + STG_A;
            const int t4 = lane & 3, gid = lane >> 2;
            // meta: thread t4 -> row gid + 8*(t4&1), words (t4>>1) of op0/op1.
            // Permuted 16B row chunk: [w0, w2 | w1, w3] -> one LDS.64 each.
            uint2 me[4];
#pragma unroll
            for (int mb = 0; mb < 4; mb++) {
                int row = wm + mb * 16 + gid + (t4 & 1) * 8;
                me[mb] = *(const uint2*)(mB + row * 16 + (t4 >> 1) * 8);
            }
#pragma unroll
            for (int c = 0; c < 2; c++) {
                uint32_t a[4][4];
#pragma unroll
                for (int mb = 0; mb < 4; mb++)
                    // matrices: (rows0-7,chunk0)(rows8-15,chunk0)(rows0-7,chunk1)(rows8-15,chunk1)
                    ldmatrix_x4(a[mb],
                        aB + (wm + mb * 16 + (lane & 7) + ((lane >> 3) & 1) * 8) * 144
                           + c * 32 + (lane >> 4) * 16);
                uint32_t bq[8][4];
#pragma unroll
                for (int nb = 0; nb < 8; nb++)
                    // matrices: cols0-7 x k-chunks 0..3 (16B each)
                    ldmatrix_x4(bq[nb],
                        bB + (wn + nb * 8 + (lane & 7)) * 144
                           + c * 64 + (lane >> 3) * 16);
#pragma unroll
                for (int mb = 0; mb < 4; mb++) {
                    uint32_t mw = c ? me[mb].y : me[mb].x;
#pragma unroll
                    for (int nb = 0; nb < 8; nb++)
                        mma_sp_s8(acc[mb][nb], a[mb], bq[nb], mw);
                }
            }
        } else {
            if (it == NSP) {   // s32 spline partials -> scaled f32
#pragma unroll
                for (int nb = 0; nb < 8; nb++) {
                    int cb = nBase + wn + nb * 8 + (lane & 3) * 2;
                    float f0 = g_scale[cb], f1 = g_scale[cb + 1];
#pragma unroll
                    for (int mb = 0; mb < 4; mb++) {
                        acc[mb][nb][0] = __float_as_int((float)acc[mb][nb][0] * f0);
                        acc[mb][nb][1] = __float_as_int((float)acc[mb][nb][1] * f1);
                        acc[mb][nb][2] = __float_as_int((float)acc[mb][nb][2] * f0);
                        acc[mb][nb][3] = __float_as_int((float)acc[mb][nb][3] * f1);
                    }
                }
            }
#pragma unroll
            for (int ks = 0; ks < 4; ks++) {
                uint32_t a[4][4], bf[8][2];
#pragma unroll
                for (int mb = 0; mb < 4; mb++)
                    ldmatrix_x4(a[mb], aB + (wm + mb * 16 + (lane & 15)) * 144
                                          + ks * 32 + ((lane >> 4) << 4));
#pragma unroll
                for (int np = 0; np < 4; np++) {
                    uint32_t q[4];
                    ldmatrix_x4(q, bB + (wn + np * 16 + (lane & 7)
                                         + ((lane >> 4) << 3)) * 144
                                      + ks * 32 + (((lane >> 3) & 1) << 4));
                    bf[np * 2][0] = q[0]; bf[np * 2][1] = q[1];
                    bf[np * 2 + 1][0] = q[2]; bf[np * 2 + 1][1] = q[3];
                }
#pragma unroll
                for (int mb = 0; mb < 4; mb++)
#pragma unroll
                    for (int nb = 0; nb < 8; nb++)
                        mma16816((float*)acc[mb][nb], a[mb], bf[nb]);
            }
        }
        __syncthreads();
    }

    const int gr = lane >> 2;
    const int tc = lane & 3;
#pragma unroll
    for (int mb = 0; mb < 4; mb++) {
#pragma unroll
        for (int nb = 0; nb < 8; nb++) {
            const float* fa = (const float*)acc[mb][nb];
            int row = mBase + wm + mb * 16 + gr;
            int col = nBase + wn + nb * 8 + tc * 2;
            *(float2*)&C[(size_t)row * N_COLS + col] = make_float2(fa[0], fa[1]);
            *(float2*)&C[(size_t)(row + 8) * N_COLS + col] = make_float2(fa[2], fa[3]);
        }
    }
}

// ---------------------------------------------------------------------------
extern "C" void kernel_launch(void* const* d_in, const int* in_sizes, int n_in,
                              void* d_out, int out_size) {
    const float* x  = (const float*)d_in[0];
    const float* bw = (const float*)d_in[1];
    const float* sw = (const float*)d_in[2];
    const float* ss = (const float*)d_in[3];
    float* out = (float*)d_out;

    build_A_kernel<<<(M_ROWS * 1024) / 256, 256>>>(x);
    pack_W_kernel<<<N_COLS, 256>>>(bw, sw, ss);

    cudaFuncSetAttribute(gemm_kernel,
                         cudaFuncAttributeMaxDynamicSharedMemorySize, SMEM_TOT);
    gemm_kernel<<<dim3(N_COLS / BN, M_ROWS / BM), 256, SMEM_TOT>>>(out);
}

// round 10
// speedup vs baseline: 1.5502x; 1.5502x over previous
#include <cuda_runtime.h>
#include <cuda_fp16.h>
#include <cstdint>

// ---------------------------------------------------------------------------
// Round-5 proven config (f16 2:4-sparse spline GEMM + dense fp16 silu GEMM,
// fused) with a deeper, single-barrier pipeline:
//   - 4-stage cp.async ring (225 KB smem)
//   - ONE __syncthreads per stage (PRE issued after the barrier, so the
//     write-target buffer is provably not being read)
// ---------------------------------------------------------------------------

#define M_ROWS 4096
#define N_COLS 1024
#define BM 128
#define BN 256
#define NSP 128
#define NDN 16
#define NTOT (NSP + NDN)

__device__ __align__(16) __half   g_A [(size_t)M_ROWS * 4096];  // comp f16 A
__device__ __align__(16) __half   g_As[(size_t)M_ROWS * 1024];  // silu
__device__ __align__(16) __half   g_B [(size_t)N_COLS * 8192];  // f16 spline B
__device__ __align__(16) __half   g_Bb[(size_t)N_COLS * 1024];  // base W
__device__ __align__(16) uint32_t g_M [(size_t)M_ROWS * 256];   // meta

__device__ __forceinline__ uint32_t smem_u32(const void* p) {
    uint32_t a;
    asm("{ .reg .u64 t; cvta.to.shared.u64 t, %1; cvt.u32.u64 %0, t; }"
        : "=r"(a) : "l"(p));
    return a;
}
__device__ __forceinline__ void cp_async16(uint32_t s, const void* g) {
    asm volatile("cp.async.cg.shared.global [%0], [%1], 16;" :: "r"(s), "l"(g));
}
__device__ __forceinline__ void cp_async8(uint32_t s, const void* g) {
    asm volatile("cp.async.ca.shared.global [%0], [%1], 8;" :: "r"(s), "l"(g));
}
__device__ __forceinline__ void ldmatrix_x4(uint32_t* r, uint32_t addr) {
    asm volatile("ldmatrix.sync.aligned.m8n8.x4.shared.b16 {%0,%1,%2,%3}, [%4];"
                 : "=r"(r[0]), "=r"(r[1]), "=r"(r[2]), "=r"(r[3]) : "r"(addr));
}
__device__ __forceinline__ void mma_sp_f16(float* d, const uint32_t* a,
                                           const uint32_t* b, uint32_t e) {
    asm volatile(
        "mma.sp::ordered_metadata.sync.aligned.m16n8k32.row.col.f32.f16.f16.f32 "
        "{%0,%1,%2,%3}, {%4,%5,%6,%7}, {%8,%9,%10,%11}, {%0,%1,%2,%3}, %12, 0x0;"
        : "+f"(d[0]), "+f"(d[1]), "+f"(d[2]), "+f"(d[3])
        : "r"(a[0]), "r"(a[1]), "r"(a[2]), "r"(a[3]),
          "r"(b[0]), "r"(b[1]), "r"(b[2]), "r"(b[3]), "r"(e));
}
__device__ __forceinline__ void mma16816(float* d, const uint32_t* a,
                                         const uint32_t* b) {
    asm volatile(
        "mma.sync.aligned.m16n8k16.row.col.f32.f16.f16.f32 "
        "{%0,%1,%2,%3}, {%4,%5,%6,%7}, {%8,%9}, {%0,%1,%2,%3};"
        : "+f"(d[0]), "+f"(d[1]), "+f"(d[2]), "+f"(d[3])
        : "r"(a[0]), "r"(a[1]), "r"(a[2]), "r"(a[3]), "r"(b[0]), "r"(b[1]));
}

// ---------------------------------------------------------------------------
__global__ void build_A_kernel(const float* __restrict__ x) {
    __shared__ unsigned char nib[512];
    const int t  = threadIdx.x;
    const int b  = blockIdx.x >> 2;
    const int i0 = (blockIdx.x & 3) << 8;

    float xv = x[b * 1024 + i0 + t];
    g_As[(size_t)b * 1024 + i0 + t] = __float2half(xv / (1.0f + __expf(-xv)));

    int j = (int)floorf((xv + 2.2f) * 2.5f);
    bool ok = (j >= 0) && (j <= 10);
    float tj = (float)(j - 3) * 0.4f - 1.0f;
    float u  = (xv - tj) * 2.5f;
    float um = 1.0f - u;
    float u2 = u * u, u3 = u2 * u;
    float W0 = um * um * um * (1.0f / 6.0f);
    float W1 = (3.0f * u3 - 6.0f * u2 + 4.0f) * (1.0f / 6.0f);
    float W2 = (-3.0f * u3 + 3.0f * u2 + 3.0f * u + 1.0f) * (1.0f / 6.0f);
    float W3 = u3 * (1.0f / 6.0f);
    if (!ok) { W0 = W1 = W2 = W3 = 0.0f; }

    int   qe  = (j + 1) & 1;
    int   pe  = j - 3 + qe;
    float We0 = qe ? W1 : W0, We1 = qe ? W3 : W2;
    int   e0  = max(min(pe >> 1, 2), 0), e1 = e0 + 1;
    float ve0 = (2 * e0 == pe) ? We0 : ((2 * e0 == pe + 2) ? We1 : 0.0f);
    float ve1 = (2 * e1 == pe) ? We0 : ((2 * e1 == pe + 2) ? We1 : 0.0f);
    int   qo  = qe ^ 1;
    int   po  = j - 3 + qo;
    float Wo0 = qo ? W1 : W0, Wo1 = qo ? W3 : W2;
    int   o0  = max(min(po >> 1, 2), 0), o1 = o0 + 1;
    float vo0 = (2 * o0 + 1 == po) ? Wo0 : ((2 * o0 + 1 == po + 2) ? Wo1 : 0.0f);
    float vo1 = (2 * o1 + 1 == po) ? Wo0 : ((2 * o1 + 1 == po + 2) ? Wo1 : 0.0f);

    __half2 hv[2];
    hv[0] = __floats2half2_rn(ve0, ve1);
    hv[1] = __floats2half2_rn(vo0, vo1);
    *(uint2*)(g_A + (size_t)b * 4096 + (size_t)(i0 + t) * 4) = *(uint2*)hv;

    nib[2 * t]     = (unsigned char)(e0 | (e1 << 2));
    nib[2 * t + 1] = (unsigned char)(o0 | (o1 << 2));
    __syncthreads();

    if (t < 64) {
        uint32_t w = 0;
#pragma unroll
        for (int q = 0; q < 8; q++) w |= (uint32_t)nib[8 * t + q] << (4 * q);
        g_M[(size_t)b * 256 + (blockIdx.x & 3) * 64 + t] = w;
    }
}

// ---------------------------------------------------------------------------
__global__ void pack_W_kernel(const float* __restrict__ bw,
                              const float* __restrict__ sw,
                              const float* __restrict__ ss) {
    const int t  = threadIdx.x;
    const int o  = blockIdx.x >> 2;
    const int i0 = (blockIdx.x & 3) << 8;
    const int e  = o * 1024 + i0 + t;

    float sc = ss[e];
    const float* swp = sw + (size_t)e * 8;
    g_Bb[e] = __float2half(bw[e]);

    __half2 h[4];
    h[0] = __floats2half2_rn(swp[0] * sc, swp[2] * sc);
    h[1] = __floats2half2_rn(swp[4] * sc, swp[6] * sc);
    h[2] = __floats2half2_rn(swp[1] * sc, swp[3] * sc);
    h[3] = __floats2half2_rn(swp[5] * sc, swp[7] * sc);
    *(uint4*)(g_B + (size_t)o * 8192 + (size_t)(i0 + t) * 8) = *(uint4*)h;
}

// ---------------------------------------------------------------------------
// GEMM: 128x256 tile, 8 warps (2x4), warp tile 64x64, 4-stage cp.async ring,
// single barrier per stage. Stages 0..127: f16 sparse; 128..143: dense silu.
// ---------------------------------------------------------------------------
#define STG_A (128 * 144)
#define STG_B (256 * 144)
#define STG_M 1024
#define STG   (STG_A + STG_B + STG_M)   // 56320
#define NBUF  4
#define SMEM_TOT (NBUF * STG)           // 225280

__global__ void __launch_bounds__(256, 1)
gemm_kernel(float* __restrict__ C) {
    extern __shared__ char smc[];
    const uint32_t sb = smem_u32(smc);
    const int tid  = threadIdx.x;
    const int wid  = tid >> 5;
    const int lane = tid & 31;
    const int wm   = (wid >> 2) * 64;
    const int wn   = (wid & 3) * 64;
    const int mBase = blockIdx.y * BM;
    const int nBase = blockIdx.x * BN;

    float acc[4][8][4];
#pragma unroll
    for (int mb = 0; mb < 4; mb++)
#pragma unroll
        for (int nb = 0; nb < 8; nb++)
#pragma unroll
            for (int r = 0; r < 4; r++) acc[mb][nb][r] = 0.0f;

#define PRE(buf, it)                                                           \
    do {                                                                       \
        uint32_t d0 = sb + (buf) * STG;                                        \
        if ((it) < NSP) {                                                      \
            _Pragma("unroll")                                                  \
            for (int u = 0; u < 2; u++) {                                      \
                int f = tid + u * 256, r = f >> 2, q = f & 3;                  \
                cp_async16(d0 + r * 144 + q * 16,                              \
                    (const char*)g_A + (size_t)(mBase + r) * 8192 +            \
                    (it) * 64 + q * 16);                                       \
            }                                                                  \
            _Pragma("unroll")                                                  \
            for (int u = 0; u < 8; u++) {                                      \
                int f = tid + u * 256, r = f >> 3, q = f & 7;                  \
                cp_async16(d0 + STG_A + r * 144 + q * 16,                      \
                    (const char*)g_B + (size_t)(nBase + r) * 16384 +           \
                    (it) * 128 + q * 16);                                      \
            }                                                                  \
            if (tid < 128)                                                     \
                cp_async8(d0 + STG_A + STG_B + tid * 8,                        \
                    (const char*)g_M + (size_t)(mBase + tid) * 1024 +          \
                    (it) * 8);                                                 \
        } else {                                                               \
            int itd = (it) - NSP;                                              \
            _Pragma("unroll")                                                  \
            for (int u = 0; u < 4; u++) {                                      \
                int f = tid + u * 256, r = f >> 3, q = f & 7;                  \
                cp_async16(d0 + r * 144 + q * 16,                              \
                    (const char*)g_As + (size_t)(mBase + r) * 2048 +           \
                    itd * 128 + q * 16);                                       \
            }                                                                  \
            _Pragma("unroll")                                                  \
            for (int u = 0; u < 8; u++) {                                      \
                int f = tid + u * 256, r = f >> 3, q = f & 7;                  \
                cp_async16(d0 + STG_A + r * 144 + q * 16,                      \
                    (const char*)g_Bb + (size_t)(nBase + r) * 2048 +           \
                    itd * 128 + q * 16);                                       \
            }                                                                  \
        }                                                                      \
        asm volatile("cp.async.commit_group;" ::: "memory");                   \
    } while (0)

    PRE(0, 0);
    PRE(1, 1);
    PRE(2, 2);

    for (int it = 0; it < NTOT; it++) {
        const int buf = it & 3;
        // make group `it` visible (groups it..it+2 may be outstanding)
        if (it < NTOT - 2) {
            asm volatile("cp.async.wait_group 2;" ::: "memory");
        } else if (it == NTOT - 2) {
            asm volatile("cp.async.wait_group 1;" ::: "memory");
        } else {
            asm volatile("cp.async.wait_group 0;" ::: "memory");
        }
        __syncthreads();   // single barrier per stage

        // prefetch stage it+3 into buf (it+3)&3 == (it-1)&3 — that buffer's
        // readers (stage it-1) are provably done after the barrier above.
        if (it + 3 < NTOT) PRE((it + 3) & 3, it + 3);

        const uint32_t aB = sb + buf * STG;
        const uint32_t bB = aB + STG_A;

        if (it < NSP) {
            const char* mB = smc + buf * STG + STG_A + STG_B;
#pragma unroll
            for (int c = 0; c < 2; c++) {
                uint32_t me[4];
#pragma unroll
                for (int mb = 0; mb < 4; mb++) {
                    int r0 = wm + mb * 16 + (lane >> 2);
                    uint32_t w0 = *(const uint32_t*)(mB + r0 * 8 + c * 4);
                    uint32_t w1 = *(const uint32_t*)(mB + (r0 + 8) * 8 + c * 4);
                    me[mb] = (lane & 1) ? ((w0 >> 16) | (w1 & 0xFFFF0000u))
                                        : ((w0 & 0xFFFFu) | (w1 << 16));
                }
                uint32_t a[4][4];
#pragma unroll
                for (int mb = 0; mb < 4; mb++)
                    ldmatrix_x4(a[mb], aB + (wm + mb * 16 + (lane & 15)) * 144
                                          + c * 32 + ((lane >> 4) << 4));
                uint32_t bq[8][4];
#pragma unroll
                for (int nb = 0; nb < 8; nb++)
                    ldmatrix_x4(bq[nb], bB + (wn + nb * 8 + (lane & 7)) * 144
                                           + c * 64 + ((lane >> 3) << 4));
#pragma unroll
                for (int mb = 0; mb < 4; mb++)
#pragma unroll
                    for (int nb = 0; nb < 8; nb++)
                        mma_sp_f16(acc[mb][nb], a[mb], bq[nb], me[mb]);
            }
        } else {
#pragma unroll
            for (int ks = 0; ks < 4; ks++) {
                uint32_t a[4][4], bf[8][2];
#pragma unroll
                for (int mb = 0; mb < 4; mb++)
                    ldmatrix_x4(a[mb], aB + (wm + mb * 16 + (lane & 15)) * 144
                                          + ks * 32 + ((lane >> 4) << 4));
#pragma unroll
                for (int np = 0; np < 4; np++) {
                    uint32_t q[4];
                    ldmatrix_x4(q, bB + (wn + np * 16 + (lane & 7)
                                         + ((lane >> 4) << 3)) * 144
                                      + ks * 32 + (((lane >> 3) & 1) << 4));
                    bf[np * 2][0] = q[0]; bf[np * 2][1] = q[1];
                    bf[np * 2 + 1][0] = q[2]; bf[np * 2 + 1][1] = q[3];
                }
#pragma unroll
                for (int mb = 0; mb < 4; mb++)
#pragma unroll
                    for (int nb = 0; nb < 8; nb++)
                        mma16816(acc[mb][nb], a[mb], bf[nb]);
            }
        }
    }

    __syncthreads();   // all stages done before epilogue (paranoia, cheap)

    const int gr = lane >> 2;
    const int tc = lane & 3;
#pragma unroll
    for (int mb = 0; mb < 4; mb++) {
#pragma unroll
        for (int nb = 0; nb < 8; nb++) {
            int row = mBase + wm + mb * 16 + gr;
            int col = nBase + wn + nb * 8 + tc * 2;
            *(float2*)&C[(size_t)row * N_COLS + col] =
                make_float2(acc[mb][nb][0], acc[mb][nb][1]);
            *(float2*)&C[(size_t)(row + 8) * N_COLS + col] =
                make_float2(acc[mb][nb][2], acc[mb][nb][3]);
        }
    }
}

// ---------------------------------------------------------------------------
extern "C" void kernel_launch(void* const* d_in, const int* in_sizes, int n_in,
                              void* d_out, int out_size) {
    const float* x  = (const float*)d_in[0];
    const float* bw = (const float*)d_in[1];
    const float* sw = (const float*)d_in[2];
    const float* ss = (const float*)d_in[3];
    float* out = (float*)d_out;

    build_A_kernel<<<(M_ROWS * 1024) / 256, 256>>>(x);
    pack_W_kernel<<<(N_COLS * 1024) / 256, 256>>>(bw, sw, ss);

    cudaFuncSetAttribute(gemm_kernel,
                         cudaFuncAttributeMaxDynamicSharedMemorySize, SMEM_TOT);
    gemm_kernel<<<dim3(N_COLS / BN, M_ROWS / BM), 256, SMEM_TOT>>>(out);
}

// round 11
// speedup vs baseline: 1.6271x; 1.0496x over previous
#include <cuda_runtime.h>
#include <cuda_fp16.h>
#include <cstdint>

// ---------------------------------------------------------------------------
// f16 2:4-sparse spline GEMM + dense fp16 silu GEMM (round-10 compute path),
// re-scheduled as a LINE-CUT over 148 CTAs: 128 tiles x 144 stages = 18432
// stage-units cut into 148 equal ranges (124-125). Tile-boundary partials are
// flushed with RED.ADD into pre-zeroed C. All 148 SMs busy (was 128).
// ---------------------------------------------------------------------------

#define M_ROWS 4096
#define N_COLS 1024
#define BM 128
#define BN 256
#define NSPS 128               // sparse stages per tile
#define NSTG 144               // stages per tile (128 sparse + 16 dense)
#define NTILE 128
#define TOTALG (NTILE * NSTG)  // 18432
#define NCTA 148

__device__ __align__(16) __half   g_A [(size_t)M_ROWS * 4096];
__device__ __align__(16) __half   g_As[(size_t)M_ROWS * 1024];
__device__ __align__(16) __half   g_B [(size_t)N_COLS * 8192];
__device__ __align__(16) __half   g_Bb[(size_t)N_COLS * 1024];
__device__ __align__(16) uint32_t g_M [(size_t)M_ROWS * 256];

__device__ __forceinline__ uint32_t smem_u32(const void* p) {
    uint32_t a;
    asm("{ .reg .u64 t; cvta.to.shared.u64 t, %1; cvt.u32.u64 %0, t; }"
        : "=r"(a) : "l"(p));
    return a;
}
__device__ __forceinline__ void cp_async16(uint32_t s, const void* g) {
    asm volatile("cp.async.cg.shared.global [%0], [%1], 16;" :: "r"(s), "l"(g));
}
__device__ __forceinline__ void cp_async8(uint32_t s, const void* g) {
    asm volatile("cp.async.ca.shared.global [%0], [%1], 8;" :: "r"(s), "l"(g));
}
__device__ __forceinline__ void ldmatrix_x4(uint32_t* r, uint32_t addr) {
    asm volatile("ldmatrix.sync.aligned.m8n8.x4.shared.b16 {%0,%1,%2,%3}, [%4];"
                 : "=r"(r[0]), "=r"(r[1]), "=r"(r[2]), "=r"(r[3]) : "r"(addr));
}
__device__ __forceinline__ void mma_sp_f16(float* d, const uint32_t* a,
                                           const uint32_t* b, uint32_t e) {
    asm volatile(
        "mma.sp::ordered_metadata.sync.aligned.m16n8k32.row.col.f32.f16.f16.f32 "
        "{%0,%1,%2,%3}, {%4,%5,%6,%7}, {%8,%9,%10,%11}, {%0,%1,%2,%3}, %12, 0x0;"
        : "+f"(d[0]), "+f"(d[1]), "+f"(d[2]), "+f"(d[3])
        : "r"(a[0]), "r"(a[1]), "r"(a[2]), "r"(a[3]),
          "r"(b[0]), "r"(b[1]), "r"(b[2]), "r"(b[3]), "r"(e));
}
__device__ __forceinline__ void mma16816(float* d, const uint32_t* a,
                                         const uint32_t* b) {
    asm volatile(
        "mma.sync.aligned.m16n8k16.row.col.f32.f16.f16.f32 "
        "{%0,%1,%2,%3}, {%4,%5,%6,%7}, {%8,%9}, {%0,%1,%2,%3};"
        : "+f"(d[0]), "+f"(d[1]), "+f"(d[2]), "+f"(d[3])
        : "r"(a[0]), "r"(a[1]), "r"(a[2]), "r"(a[3]), "r"(b[0]), "r"(b[1]));
}

// ---------------------------------------------------------------------------
// Prep kernel: blocks [0,16384) build A (+ zero C); blocks [16384,20480) pack W.
// ---------------------------------------------------------------------------
__global__ void prep_kernel(const float* __restrict__ x,
                            const float* __restrict__ bw,
                            const float* __restrict__ sw,
                            const float* __restrict__ ss,
                            float* __restrict__ C) {
    const int t = threadIdx.x;
    if (blockIdx.x < 16384) {
        __shared__ unsigned char nib[512];
        const int b  = blockIdx.x >> 2;
        const int i0 = (blockIdx.x & 3) << 8;

        C[blockIdx.x * 256 + t] = 0.0f;   // zero output for RED epilogues

        float xv = x[b * 1024 + i0 + t];
        g_As[(size_t)b * 1024 + i0 + t] = __float2half(xv / (1.0f + __expf(-xv)));

        int j = (int)floorf((xv + 2.2f) * 2.5f);
        bool ok = (j >= 0) && (j <= 10);
        float tj = (float)(j - 3) * 0.4f - 1.0f;
        float u  = (xv - tj) * 2.5f;
        float um = 1.0f - u;
        float u2 = u * u, u3 = u2 * u;
        float W0 = um * um * um * (1.0f / 6.0f);
        float W1 = (3.0f * u3 - 6.0f * u2 + 4.0f) * (1.0f / 6.0f);
        float W2 = (-3.0f * u3 + 3.0f * u2 + 3.0f * u + 1.0f) * (1.0f / 6.0f);
        float W3 = u3 * (1.0f / 6.0f);
        if (!ok) { W0 = W1 = W2 = W3 = 0.0f; }

        int   qe  = (j + 1) & 1;
        int   pe  = j - 3 + qe;
        float We0 = qe ? W1 : W0, We1 = qe ? W3 : W2;
        int   e0  = max(min(pe >> 1, 2), 0), e1 = e0 + 1;
        float ve0 = (2 * e0 == pe) ? We0 : ((2 * e0 == pe + 2) ? We1 : 0.0f);
        float ve1 = (2 * e1 == pe) ? We0 : ((2 * e1 == pe + 2) ? We1 : 0.0f);
        int   qo  = qe ^ 1;
        int   po  = j - 3 + qo;
        float Wo0 = qo ? W1 : W0, Wo1 = qo ? W3 : W2;
        int   o0  = max(min(po >> 1, 2), 0), o1 = o0 + 1;
        float vo0 = (2 * o0 + 1 == po) ? Wo0 : ((2 * o0 + 1 == po + 2) ? Wo1 : 0.0f);
        float vo1 = (2 * o1 + 1 == po) ? Wo0 : ((2 * o1 + 1 == po + 2) ? Wo1 : 0.0f);

        __half2 hv[2];
        hv[0] = __floats2half2_rn(ve0, ve1);
        hv[1] = __floats2half2_rn(vo0, vo1);
        *(uint2*)(g_A + (size_t)b * 4096 + (size_t)(i0 + t) * 4) = *(uint2*)hv;

        nib[2 * t]     = (unsigned char)(e0 | (e1 << 2));
        nib[2 * t + 1] = (unsigned char)(o0 | (o1 << 2));
        __syncthreads();

        if (t < 64) {
            uint32_t w = 0;
#pragma unroll
            for (int q = 0; q < 8; q++) w |= (uint32_t)nib[8 * t + q] << (4 * q);
            g_M[(size_t)b * 256 + (blockIdx.x & 3) * 64 + t] = w;
        }
    } else {
        const int bid = blockIdx.x - 16384;
        const int o  = bid >> 2;
        const int i0 = (bid & 3) << 8;
        const int e  = o * 1024 + i0 + t;

        float sc = ss[e];
        const float* swp = sw + (size_t)e * 8;
        g_Bb[e] = __float2half(bw[e]);

        __half2 h[4];
        h[0] = __floats2half2_rn(swp[0] * sc, swp[2] * sc);
        h[1] = __floats2half2_rn(swp[4] * sc, swp[6] * sc);
        h[2] = __floats2half2_rn(swp[1] * sc, swp[3] * sc);
        h[3] = __floats2half2_rn(swp[5] * sc, swp[7] * sc);
        *(uint4*)(g_B + (size_t)o * 8192 + (size_t)(i0 + t) * 8) = *(uint4*)h;
    }
}

// ---------------------------------------------------------------------------
// GEMM: 148 CTAs, each walks stage-range [g0,g1) of the global work line.
// Stage G -> tile t = G/144 (mB = (t>>2)*128, nB = (t&3)*256), s = G%144.
// s<128: f16 sparse stage; else dense silu stage. Tile-boundary partials are
// flushed via atomicAdd (REDG). 4-stage cp.async ring, one barrier per stage.
// ---------------------------------------------------------------------------
#define STG_A (128 * 144)
#define STG_B (256 * 144)
#define STG_M 1024
#define STG   (STG_A + STG_B + STG_M)   // 56320
#define SMEM_TOT (4 * STG)              // 225280

__global__ void __launch_bounds__(256, 1)
gemm_kernel(float* __restrict__ C) {
    extern __shared__ char smc[];
    const uint32_t sb = smem_u32(smc);
    const int tid  = threadIdx.x;
    const int wid  = tid >> 5;
    const int lane = tid & 31;
    const int wm   = (wid >> 2) * 64;
    const int wn   = (wid & 3) * 64;

    const int r  = blockIdx.x;
    const int g0 = (4608 * r) / 37;        // = TOTALG*r/148
    const int g1 = (4608 * (r + 1)) / 37;

    float acc[4][8][4];
#pragma unroll
    for (int mb = 0; mb < 4; mb++)
#pragma unroll
        for (int nb = 0; nb < 8; nb++)
#pragma unroll
            for (int q = 0; q < 4; q++) acc[mb][nb][q] = 0.0f;

#define PRE(buf, G)                                                            \
    do {                                                                       \
        int t2 = (G) / NSTG;                                                   \
        int ss = (G) - t2 * NSTG;                                              \
        int mB = (t2 >> 2) * BM;                                               \
        int nB = (t2 & 3) * BN;                                                \
        uint32_t d0 = sb + (buf) * STG;                                        \
        if (ss < NSPS) {                                                       \
            _Pragma("unroll")                                                  \
            for (int u = 0; u < 2; u++) {                                      \
                int f = tid + u * 256, rr = f >> 2, q = f & 3;                 \
                cp_async16(d0 + rr * 144 + q * 16,                             \
                    (const char*)g_A + (size_t)(mB + rr) * 8192 +              \
                    ss * 64 + q * 16);                                         \
            }                                                                  \
            _Pragma("unroll")                                                  \
            for (int u = 0; u < 8; u++) {                                      \
                int f = tid + u * 256, rr = f >> 3, q = f & 7;                 \
                cp_async16(d0 + STG_A + rr * 144 + q * 16,                     \
                    (const char*)g_B + (size_t)(nB + rr) * 16384 +             \
                    ss * 128 + q * 16);                                        \
            }                                                                  \
            if (tid < 128)                                                     \
                cp_async8(d0 + STG_A + STG_B + tid * 8,                        \
                    (const char*)g_M + (size_t)(mB + tid) * 1024 + ss * 8);    \
        } else {                                                               \
            int itd = ss - NSPS;                                               \
            _Pragma("unroll")                                                  \
            for (int u = 0; u < 4; u++) {                                      \
                int f = tid + u * 256, rr = f >> 3, q = f & 7;                 \
                cp_async16(d0 + rr * 144 + q * 16,                             \
                    (const char*)g_As + (size_t)(mB + rr) * 2048 +             \
                    itd * 128 + q * 16);                                       \
            }                                                                  \
            _Pragma("unroll")                                                  \
            for (int u = 0; u < 8; u++) {                                      \
                int f = tid + u * 256, rr = f >> 3, q = f & 7;                 \
                cp_async16(d0 + STG_A + rr * 144 + q * 16,                     \
                    (const char*)g_Bb + (size_t)(nB + rr) * 2048 +             \
                    itd * 128 + q * 16);                                       \
            }                                                                  \
        }                                                                      \
        asm volatile("cp.async.commit_group;" ::: "memory");                   \
    } while (0)

// Flush partial accumulators for tile tt via RED.ADD, then clear.
#define EPI_RED(tt)                                                            \
    do {                                                                       \
        int mB = ((tt) >> 2) * BM + wm + (lane >> 2);                          \
        int nB = ((tt) & 3) * BN + wn + (lane & 3) * 2;                        \
        _Pragma("unroll")                                                      \
        for (int mb = 0; mb < 4; mb++) {                                       \
            _Pragma("unroll")                                                  \
            for (int nb = 0; nb < 8; nb++) {                                   \
                int row = mB + mb * 16;                                        \
                int col = nB + nb * 8;                                         \
                atomicAdd(&C[(size_t)row * N_COLS + col],       acc[mb][nb][0]);\
                atomicAdd(&C[(size_t)row * N_COLS + col + 1],   acc[mb][nb][1]);\
                atomicAdd(&C[(size_t)(row + 8) * N_COLS + col],     acc[mb][nb][2]);\
                atomicAdd(&C[(size_t)(row + 8) * N_COLS + col + 1], acc[mb][nb][3]);\
                acc[mb][nb][0] = 0.0f; acc[mb][nb][1] = 0.0f;                  \
                acc[mb][nb][2] = 0.0f; acc[mb][nb][3] = 0.0f;                  \
            }                                                                  \
        }                                                                      \
    } while (0)

    PRE(0, g0);
    if (g0 + 1 < g1) PRE(1, g0 + 1);
    if (g0 + 2 < g1) PRE(2, g0 + 2);

    for (int G = g0; G < g1; G++) {
        const int buf = (G - g0) & 3;
        if (G + 2 < g1) {
            asm volatile("cp.async.wait_group 2;" ::: "memory");
        } else if (G + 1 < g1) {
            asm volatile("cp.async.wait_group 1;" ::: "memory");
        } else {
            asm volatile("cp.async.wait_group 0;" ::: "memory");
        }
        __syncthreads();

        if (G + 3 < g1) PRE((G + 3 - g0) & 3, G + 3);

        const int t = G / NSTG;
        const int s = G - t * NSTG;
        if (s == 0 && G > g0) EPI_RED(t - 1);   // flush previous tile partial

        const uint32_t aB = sb + buf * STG;
        const uint32_t bB = aB + STG_A;

        if (s < NSPS) {
            const char* mB = smc + buf * STG + STG_A + STG_B;
#pragma unroll
            for (int c = 0; c < 2; c++) {
                uint32_t me[4];
#pragma unroll
                for (int mb = 0; mb < 4; mb++) {
                    int r0 = wm + mb * 16 + (lane >> 2);
                    uint32_t w0 = *(const uint32_t*)(mB + r0 * 8 + c * 4);
                    uint32_t w1 = *(const uint32_t*)(mB + (r0 + 8) * 8 + c * 4);
                    me[mb] = (lane & 1) ? ((w0 >> 16) | (w1 & 0xFFFF0000u))
                                        : ((w0 & 0xFFFFu) | (w1 << 16));
                }
                uint32_t a[4][4];
#pragma unroll
                for (int mb = 0; mb < 4; mb++)
                    ldmatrix_x4(a[mb], aB + (wm + mb * 16 + (lane & 15)) * 144
                                          + c * 32 + ((lane >> 4) << 4));
                uint32_t bq[8][4];
#pragma unroll
                for (int nb = 0; nb < 8; nb++)
                    ldmatrix_x4(bq[nb], bB + (wn + nb * 8 + (lane & 7)) * 144
                                           + c * 64 + ((lane >> 3) << 4));
#pragma unroll
                for (int mb = 0; mb < 4; mb++)
#pragma unroll
                    for (int nb = 0; nb < 8; nb++)
                        mma_sp_f16(acc[mb][nb], a[mb], bq[nb], me[mb]);
            }
        } else {
#pragma unroll
            for (int ks = 0; ks < 4; ks++) {
                uint32_t a[4][4], bf[8][2];
#pragma unroll
                for (int mb = 0; mb < 4; mb++)
                    ldmatrix_x4(a[mb], aB + (wm + mb * 16 + (lane & 15)) * 144
                                          + ks * 32 + ((lane >> 4) << 4));
#pragma unroll
                for (int np = 0; np < 4; np++) {
                    uint32_t q[4];
                    ldmatrix_x4(q, bB + (wn + np * 16 + (lane & 7)
                                         + ((lane >> 4) << 3)) * 144
                                      + ks * 32 + (((lane >> 3) & 1) << 4));
                    bf[np * 2][0] = q[0]; bf[np * 2][1] = q[1];
                    bf[np * 2 + 1][0] = q[2]; bf[np * 2 + 1][1] = q[3];
                }
#pragma unroll
                for (int mb = 0; mb < 4; mb++)
#pragma unroll
                    for (int nb = 0; nb < 8; nb++)
                        mma16816(acc[mb][nb], a[mb], bf[nb]);
            }
        }
    }

    EPI_RED((g1 - 1) / NSTG);   // flush final tile partial
}

// ---------------------------------------------------------------------------
extern "C" void kernel_launch(void* const* d_in, const int* in_sizes, int n_in,
                              void* d_out, int out_size) {
    const float* x  = (const float*)d_in[0];
    const float* bw = (const float*)d_in[1];
    const float* sw = (const float*)d_in[2];
    const float* ss = (const float*)d_in[3];
    float* out = (float*)d_out;

    prep_kernel<<<16384 + 4096, 256>>>(x, bw, sw, ss, out);

    cudaFuncSetAttribute(gemm_kernel,
                         cudaFuncAttributeMaxDynamicSharedMemorySize, SMEM_TOT);
    gemm_kernel<<<NCTA, 256, SMEM_TOT>>>(out);
}